// round 1
// baseline (speedup 1.0000x reference)
#include <cuda_runtime.h>
#include <cstdint>

#define NB 16
#define NA 200000
#define NK 300
#define CAP 16384
#define NW 10   // ceil(300/32) suppression-mask words

// Scratch (no allocations allowed): per-batch candidate keys + counters.
__device__ int g_count[NB];
__device__ unsigned long long g_cand[NB * CAP];

__global__ void k_reset() {
    if (threadIdx.x < NB) g_count[threadIdx.x] = 0;
}

// Pass 1: score = sigmoid(conf); append (score_bits<<32 | ~anchor_idx) for score>=0.5.
// B*A = 3,200,000; A % 32 == 0 so each warp is batch-uniform -> warp-aggregated atomics.
__global__ void k_scan(const float* __restrict__ conf) {
    int idx = blockIdx.x * blockDim.x + threadIdx.x;
    if (idx >= NB * NA) return;
    float x = conf[idx];
    float s = 1.0f / (1.0f + expf(-x));
    bool pred = (s >= 0.5f);
    unsigned ballot = __ballot_sync(0xffffffffu, pred);
    if (pred) {
        int b = idx / NA;
        int lane = threadIdx.x & 31;
        int leader = __ffs(ballot) - 1;
        int base = 0;
        if (lane == leader) base = atomicAdd(&g_count[b], __popc(ballot));
        base = __shfl_sync(ballot, base, leader);
        int pos = base + __popc(ballot & ((1u << lane) - 1u));
        if (pos < CAP) {
            unsigned a = (unsigned)(idx - b * NA);
            unsigned long long key =
                ((unsigned long long)__float_as_uint(s) << 32) |
                (unsigned long long)(0xFFFFFFFFu - a);   // tie-break: lower idx wins
            g_cand[b * CAP + pos] = key;
        }
    }
}

// Pass 2: one block per batch. Bitonic full sort (desc) == lax.top_k order.
// Then decode top-300 boxes, build IoU suppression bitmasks, warp-serial greedy NMS, write outputs.
extern __shared__ unsigned long long skeys[];

__global__ void __launch_bounds__(1024, 1)
k_select(const float* __restrict__ p_loc,
         const float* __restrict__ anchors,
         float* __restrict__ out) {
    __shared__ float sx1[NK], sy1[NK], sx2[NK], sy2[NK], ssc[NK], sarea[NK];
    __shared__ unsigned smask[NK * NW];
    __shared__ unsigned svalid[NW];
    __shared__ unsigned srem[NW];

    const int b = blockIdx.x;
    const int tid = threadIdx.x;

    int count = g_count[b];
    if (count > CAP) count = CAP;
    int N = 512;
    while (N < count) N <<= 1;

    for (int i = tid; i < N; i += 1024)
        skeys[i] = (i < count) ? g_cand[b * CAP + i] : 0ULL;
    if (tid < NW) svalid[tid] = 0u;
    __syncthreads();

    // Bitonic sort, descending.
    for (int k = 2; k <= N; k <<= 1) {
        for (int j = k >> 1; j > 0; j >>= 1) {
            for (int i = tid; i < N; i += 1024) {
                int ixj = i ^ j;
                if (ixj > i) {
                    unsigned long long a0 = skeys[i], a1 = skeys[ixj];
                    bool up = ((i & k) == 0);
                    if ((a0 < a1) == up) { skeys[i] = a1; skeys[ixj] = a0; }
                }
            }
            __syncthreads();
        }
    }

    // Decode boxes for top-K slots.
    if (tid < NK) {
        unsigned long long key = skeys[tid];
        float s = __uint_as_float((unsigned)(key >> 32));
        bool valid = (tid < count) && (s >= 0.5f);
        float x1 = 0.f, y1 = 0.f, x2 = 0.f, y2 = 0.f, area = 0.f;
        if (valid) {
            int a = (int)(0xFFFFFFFFu - (unsigned)(key & 0xFFFFFFFFu));
            float4 an = ((const float4*)anchors)[a];
            const float4 lv = ((const float4*)p_loc)[(size_t)b * NA + a];
            float cx = an.x + lv.x * 0.1f * an.z;
            float cy = an.y + lv.y * 0.1f * an.w;
            float w = an.z * expf(lv.z * 0.2f);
            float h = an.w * expf(lv.w * 0.2f);
            x1 = cx - 0.5f * w; y1 = cy - 0.5f * h;
            x2 = cx + 0.5f * w; y2 = cy + 0.5f * h;
            area = fmaxf(x2 - x1, 0.f) * fmaxf(y2 - y1, 0.f);
            atomicOr(&svalid[tid >> 5], 1u << (tid & 31));
        }
        sx1[tid] = x1; sy1[tid] = y1; sx2[tid] = x2; sy2[tid] = y2;
        ssc[tid] = s; sarea[tid] = area;
    }
    __syncthreads();

    // Suppression bitmasks: smask[i][w] bit j-in-word set iff (j>i && iou(i,j)>THR_NMS).
    for (int t = tid; t < NK * NW; t += 1024) {
        int i = t / NW, w = t % NW;
        float ix1 = sx1[i], iy1 = sy1[i], ix2 = sx2[i], iy2 = sy2[i], ia = sarea[i];
        unsigned m = 0;
        int jbase = w * 32;
        #pragma unroll 8
        for (int bit = 0; bit < 32; bit++) {
            int j = jbase + bit;
            if (j < NK && j > i) {
                float lt0 = fmaxf(ix1, sx1[j]), lt1 = fmaxf(iy1, sy1[j]);
                float rb0 = fminf(ix2, sx2[j]), rb1 = fminf(iy2, sy2[j]);
                float iw = fmaxf(rb0 - lt0, 0.f), ih = fmaxf(rb1 - lt1, 0.f);
                float inter = iw * ih;
                float uni = fmaxf(ia + sarea[j] - inter, 1e-9f);
                if (inter > 0.3f * uni) m |= (1u << bit);
            }
        }
        smask[i * NW + w] = m;
    }
    __syncthreads();

    // Greedy resolution on warp 0: rem starts as ~valid (invalid == pre-removed).
    if (tid < 32) {
        int lane = tid;
        unsigned rem = (lane < NW) ? ~svalid[lane] : 0xFFFFFFFFu;
        for (int i = 0; i < NK; i++) {
            unsigned rw = __shfl_sync(0xffffffffu, rem, i >> 5);
            if (!((rw >> (i & 31)) & 1u)) {       // keep[i] -> suppress its mask
                if (lane < NW) rem |= smask[i * NW + lane];
            }
        }
        if (lane < NW) srem[lane] = rem;
    }
    __syncthreads();

    // Outputs: [ids(4800) | boxes(19200) | labels(4800) | scores(4800) | keep(4800)]
    if (tid < NK) {
        bool keep = !((srem[tid >> 5] >> (tid & 31)) & 1u);
        int slot = b * NK + tid;
        float kf = keep ? 1.0f : 0.0f;
        out[slot] = keep ? (float)b : -1.0f;
        float* ob = out + NB * NK + slot * 4;
        ob[0] = sx1[tid] * kf;
        ob[1] = sy1[tid] * kf;
        ob[2] = sx2[tid] * kf;
        ob[3] = sy2[tid] * kf;
        out[NB * NK * 5 + slot] = kf;             // labels
        out[NB * NK * 6 + slot] = ssc[tid] * kf;  // scores
        out[NB * NK * 7 + slot] = kf;             // keep
    }
}

extern "C" void kernel_launch(void* const* d_in, const int* in_sizes, int n_in,
                              void* d_out, int out_size) {
    const float* p_loc   = (const float*)d_in[0];
    const float* p_conf  = (const float*)d_in[1];
    // d_in[2] = p_landms: dead compute in reference, intentionally unread.
    const float* anchors = (const float*)d_in[3];
    float* out = (float*)d_out;

    cudaFuncSetAttribute(k_select, cudaFuncAttributeMaxDynamicSharedMemorySize,
                         CAP * (int)sizeof(unsigned long long));

    k_reset<<<1, 32>>>();
    k_scan<<<(NB * NA + 255) / 256, 256>>>(p_conf);
    k_select<<<NB, 1024, CAP * sizeof(unsigned long long)>>>(p_loc, anchors, out);
}

// round 2
// speedup vs baseline: 1.7049x; 1.7049x over previous
#include <cuda_runtime.h>
#include <cstdint>

#define NB 16
#define NA 200000
#define NK 300
#define CAP 16384
#define FCAP 4096
#define NW 10          // ceil(300/32) suppression-mask words
#define NBINS 2048
#define FULLM 0xffffffffu

typedef unsigned long long ull;

// Scratch (no allocations allowed): per-batch candidate anchor indices + counters.
__device__ int g_count[NB];          // zero-initialized at module load; k_select re-zeroes
__device__ int g_idx[NB * CAP];

// ---------------------------------------------------------------------------
// Pass 1: pure streaming scan of p_conf (12.8 MB). sigmoid(x)>=0.5 <=> x>=0.
// Append anchor index per batch with match_any-aggregated atomics (warps may
// straddle batch boundaries: 200000 % 128 != 0).
// ---------------------------------------------------------------------------
__global__ void k_scan(const float4* __restrict__ conf4) {
    int i = blockIdx.x * blockDim.x + threadIdx.x;   // 0 .. NB*NA/4-1 (exact grid)
    float4 v = conf4[i];
    int base = i * 4;
    int lane = threadIdx.x & 31;
    unsigned lt = (1u << lane) - 1u;
    #pragma unroll
    for (int e = 0; e < 4; e++) {
        float x = (e == 0) ? v.x : (e == 1) ? v.y : (e == 2) ? v.z : v.w;
        bool pred = (x >= 0.0f);
        unsigned act = __ballot_sync(FULLM, pred);
        if (pred) {
            int idx = base + e;
            int b = idx / NA;
            unsigned peers = __match_any_sync(act, b);
            int leader = __ffs(peers) - 1;
            int rank = __popc(peers & lt);
            int pos0 = 0;
            if (lane == leader) pos0 = atomicAdd(&g_count[b], __popc(peers));
            pos0 = __shfl_sync(peers, pos0, leader);
            int pos = pos0 + rank;
            if (pos < CAP) g_idx[b * CAP + pos] = idx - b * NA;
        }
    }
}

// ---------------------------------------------------------------------------
// Pass 2: one block per batch.
//   build (sigmoid_bits<<32 | ~idx) keys  ->  2048-bin radix select (rank 300)
//   -> compact -> tiny bitonic sort -> decode boxes -> IoU bitmask NMS -> out
// ---------------------------------------------------------------------------
extern __shared__ ull dynsm[];   // [CAP] skeys (fallback sort) + [FCAP] cand2

__device__ __forceinline__ void bitonic_desc(ull* a, int N, int tid) {
    for (int k = 2; k <= N; k <<= 1) {
        for (int j = k >> 1; j > 0; j >>= 1) {
            for (int i = tid; i < N; i += 1024) {
                int ixj = i ^ j;
                if (ixj > i) {
                    ull a0 = a[i], a1 = a[ixj];
                    bool up = ((i & k) == 0);
                    if ((a0 < a1) == up) { a[i] = a1; a[ixj] = a0; }
                }
            }
            __syncthreads();
        }
    }
}

__global__ void __launch_bounds__(1024, 1)
k_select(const float* __restrict__ conf,
         const float* __restrict__ p_loc,
         const float* __restrict__ anchors,
         float* __restrict__ out) {
    __shared__ unsigned hist[NBINS];
    __shared__ unsigned wsum[32];
    __shared__ int sT, scount2;
    __shared__ float sx1[NK], sy1[NK], sx2[NK], sy2[NK], ssc[NK], sarea[NK];
    __shared__ unsigned smask[NK * NW];
    __shared__ unsigned svalid[NW];
    __shared__ unsigned srem[NW];

    ull* skeys = dynsm;
    ull* cand2 = dynsm + CAP;

    const int b = blockIdx.x;
    const int tid = threadIdx.x;

    int count = g_count[b];
    if (count > CAP) count = CAP;

    // Build keys (precise sigmoid for ~2.3% survivors only).
    for (int i = tid; i < count; i += 1024) {
        int a = g_idx[b * CAP + i];
        float x = conf[(size_t)b * NA + a];
        float s = 1.0f / (1.0f + expf(-x));
        skeys[i] = ((ull)__float_as_uint(s) << 32) |
                   (ull)(0xFFFFFFFFu - (unsigned)a);    // tie-break: lower idx wins
    }
    for (int i = tid; i < NBINS; i += 1024) hist[i] = 0;
    if (tid == 0) { sT = 0; scount2 = 0; }
    if (tid < NW) svalid[tid] = 0u;
    __syncthreads();

    // Histogram over mantissa bits [23:12] (scores all share exponent of [0.5,1)).
    for (int i = tid; i < count; i += 1024) {
        unsigned hi = (unsigned)(skeys[i] >> 32);
        int bin = min((int)((hi >> 12) - 0x3F000u), NBINS - 1);
        atomicAdd(&hist[bin], 1u);
    }
    __syncthreads();

    // Block-wide suffix scan (2 bins/thread, reverse order) to locate rank-NK bin.
    {
        int r0 = 2 * tid, r1 = 2 * tid + 1;
        unsigned h0 = hist[NBINS - 1 - r0];
        unsigned h1 = hist[NBINS - 1 - r1];
        unsigned tsum = h0 + h1;
        unsigned lane = tid & 31, wid = tid >> 5;
        unsigned inc = tsum;
        #pragma unroll
        for (int o = 1; o < 32; o <<= 1) {
            unsigned n = __shfl_up_sync(FULLM, inc, o);
            if (lane >= (unsigned)o) inc += n;
        }
        if (lane == 31) wsum[wid] = inc;
        __syncthreads();
        if (tid < 32) {
            unsigned w = wsum[tid];
            #pragma unroll
            for (int o = 1; o < 32; o <<= 1) {
                unsigned n = __shfl_up_sync(FULLM, w, o);
                if (tid >= (unsigned)o) w += n;
            }
            wsum[tid] = w;
        }
        __syncthreads();
        unsigned C0 = (wid ? wsum[wid - 1] : 0u) + (inc - tsum);  // #keys in bins > b0
        unsigned C1 = C0 + h0;
        int b0 = NBINS - 1 - r0, b1 = NBINS - 1 - r1;
        if (C0 < NK && C0 + h0 >= NK) sT = b0;
        if (C1 < NK && C1 + h1 >= NK) sT = b1;
        // if total < NK nobody fires -> sT stays 0 -> keep everything
    }
    __syncthreads();

    // Compact bin >= T.
    int T = sT;
    for (int i = tid; i < count; i += 1024) {
        unsigned hi = (unsigned)(skeys[i] >> 32);
        int bin = min((int)((hi >> 12) - 0x3F000u), NBINS - 1);
        if (bin >= T) {
            int p = atomicAdd(&scount2, 1);
            if (p < FCAP) cand2[p] = skeys[i];
        }
    }
    __syncthreads();
    int count2 = scount2;

    const ull* top;
    int len;
    if (count2 <= FCAP) {
        int N2 = 512;
        while (N2 < count2) N2 <<= 1;
        for (int i = tid; i < N2; i += 1024)
            if (i >= count2) cand2[i] = 0ULL;
        __syncthreads();
        bitonic_desc(cand2, N2, tid);
        top = cand2;
        len = count2 < NK ? count2 : NK;
    } else {
        // Pathological tie pile-up: full sort fallback.
        int N = 512;
        while (N < count) N <<= 1;
        for (int i = tid; i < N; i += 1024)
            if (i >= count) skeys[i] = 0ULL;
        __syncthreads();
        bitonic_desc(skeys, N, tid);
        top = skeys;
        len = count < NK ? count : NK;
    }

    // Decode boxes for the top-K slots.
    if (tid < NK) {
        ull key = (tid < len) ? top[tid] : 0ULL;
        float s = __uint_as_float((unsigned)(key >> 32));
        bool valid = (tid < len) && (s >= 0.5f);
        float x1 = 0.f, y1 = 0.f, x2 = 0.f, y2 = 0.f, area = 0.f;
        if (valid) {
            int a = (int)(0xFFFFFFFFu - (unsigned)(key & 0xFFFFFFFFu));
            float4 an = ((const float4*)anchors)[a];
            float4 lv = ((const float4*)p_loc)[(size_t)b * NA + a];
            float cx = an.x + lv.x * 0.1f * an.z;
            float cy = an.y + lv.y * 0.1f * an.w;
            float w = an.z * expf(lv.z * 0.2f);
            float h = an.w * expf(lv.w * 0.2f);
            x1 = cx - 0.5f * w; y1 = cy - 0.5f * h;
            x2 = cx + 0.5f * w; y2 = cy + 0.5f * h;
            area = fmaxf(x2 - x1, 0.f) * fmaxf(y2 - y1, 0.f);
            atomicOr(&svalid[tid >> 5], 1u << (tid & 31));
        }
        sx1[tid] = x1; sy1[tid] = y1; sx2[tid] = x2; sy2[tid] = y2;
        ssc[tid] = s; sarea[tid] = area;
    }
    __syncthreads();

    // Suppression bitmasks: smask[i][w] bit j set iff (j>i && iou(i,j)>0.3).
    for (int t = tid; t < NK * NW; t += 1024) {
        int i = t / NW, w = t % NW;
        float ix1 = sx1[i], iy1 = sy1[i], ix2 = sx2[i], iy2 = sy2[i], ia = sarea[i];
        unsigned m = 0;
        int jbase = w * 32;
        #pragma unroll 8
        for (int bit = 0; bit < 32; bit++) {
            int j = jbase + bit;
            if (j < NK && j > i) {
                float lt0 = fmaxf(ix1, sx1[j]), lt1 = fmaxf(iy1, sy1[j]);
                float rb0 = fminf(ix2, sx2[j]), rb1 = fminf(iy2, sy2[j]);
                float iw = fmaxf(rb0 - lt0, 0.f), ih = fmaxf(rb1 - lt1, 0.f);
                float inter = iw * ih;
                float uni = fmaxf(ia + sarea[j] - inter, 1e-9f);
                if (inter > 0.3f * uni) m |= (1u << bit);
            }
        }
        smask[i * NW + w] = m;
    }
    __syncthreads();

    // Greedy resolution on warp 0: rem starts as ~valid (invalid == pre-removed).
    if (tid < 32) {
        int lane = tid;
        unsigned rem = (lane < NW) ? ~svalid[lane] : FULLM;
        for (int i = 0; i < NK; i++) {
            unsigned rw = __shfl_sync(FULLM, rem, i >> 5);
            if (!((rw >> (i & 31)) & 1u)) {
                if (lane < NW) rem |= smask[i * NW + lane];
            }
        }
        if (lane < NW) srem[lane] = rem;
    }
    __syncthreads();

    // Outputs: [ids(4800) | boxes(19200) | labels(4800) | scores(4800) | keep(4800)]
    if (tid < NK) {
        bool keep = !((srem[tid >> 5] >> (tid & 31)) & 1u);
        int slot = b * NK + tid;
        float kf = keep ? 1.0f : 0.0f;
        out[slot] = keep ? (float)b : -1.0f;
        float* ob = out + NB * NK + slot * 4;
        ob[0] = sx1[tid] * kf;
        ob[1] = sy1[tid] * kf;
        ob[2] = sx2[tid] * kf;
        ob[3] = sy2[tid] * kf;
        out[NB * NK * 5 + slot] = kf;
        out[NB * NK * 6 + slot] = ssc[tid] * kf;
        out[NB * NK * 7 + slot] = kf;
    }

    // Reset counter for the next graph replay (module-load value is also 0).
    if (tid == 0) g_count[b] = 0;
}

extern "C" void kernel_launch(void* const* d_in, const int* in_sizes, int n_in,
                              void* d_out, int out_size) {
    const float* p_loc   = (const float*)d_in[0];
    const float* p_conf  = (const float*)d_in[1];
    // d_in[2] = p_landms: dead compute in reference, intentionally unread.
    const float* anchors = (const float*)d_in[3];
    float* out = (float*)d_out;

    static int smem_set = 0;
    if (!smem_set) {
        cudaFuncSetAttribute(k_select, cudaFuncAttributeMaxDynamicSharedMemorySize,
                             (CAP + FCAP) * (int)sizeof(ull));
        smem_set = 1;
    }

    k_scan<<<(NB * NA / 4 + 255) / 256, 256>>>((const float4*)p_conf);
    k_select<<<NB, 1024, (CAP + FCAP) * sizeof(ull)>>>(p_conf, p_loc, anchors, out);
}

// round 3
// speedup vs baseline: 3.3266x; 1.9512x over previous
#include <cuda_runtime.h>
#include <cstdint>

#define NB 16
#define NA 200000
#define NK 300
#define CAP 16384
#define FCAP 4096
#define NW 10          // ceil(300/32) suppression-mask words
#define NBINS 2048
#define FULLM 0xffffffffu

typedef unsigned long long ull;

// Scratch (no allocations allowed): per-batch candidate records + counters.
// Record = (conf_bits << 32) | anchor_idx. Order within a batch is irrelevant (sorted later).
__device__ int g_count[NB];          // zero-init at load; k_select re-zeroes each replay
__device__ ull g_cand[NB * CAP];

// ---------------------------------------------------------------------------
// Pass 1: streaming scan of p_conf. sigmoid(x)>=0.5 <=> x>=0.
// Block-aggregated append: ~24 candidates/block counted in smem, ONE global
// atomicAdd per (block, batch). Blocks cover 1024 contiguous elems; at most
// one batch boundary can fall inside a block.
// ---------------------------------------------------------------------------
__global__ void k_scan(const float4* __restrict__ conf4) {
    __shared__ int scnt[2];
    __shared__ int sbase[2];
    const int t = threadIdx.x;
    if (t < 2) scnt[t] = 0;
    __syncthreads();

    int gi = blockIdx.x * 256 + t;           // float4 index (grid exact: 800000)
    float4 v = conf4[gi];
    int e0 = gi * 4;
    int b0 = (blockIdx.x * 1024) / NA;       // batch of first elem in block
    int split = (b0 + 1) * NA;               // first elem of next batch

    ull key[4]; int pos[4]; int sel[4]; bool pred[4];
    float xs[4] = {v.x, v.y, v.z, v.w};
    #pragma unroll
    for (int e = 0; e < 4; e++) {
        pred[e] = (xs[e] >= 0.0f);
        if (pred[e]) {
            int idx = e0 + e;
            sel[e] = (idx >= split) ? 1 : 0;
            unsigned a = (unsigned)(idx - (b0 + sel[e]) * NA);
            key[e] = ((ull)__float_as_uint(xs[e]) << 32) | (ull)a;
            pos[e] = atomicAdd(&scnt[sel[e]], 1);
        }
    }
    __syncthreads();
    if (t < 2) sbase[t] = scnt[t] ? atomicAdd(&g_count[b0 + t], scnt[t]) : 0;
    __syncthreads();
    #pragma unroll
    for (int e = 0; e < 4; e++) {
        if (pred[e]) {
            int p = sbase[sel[e]] + pos[e];
            if (p < CAP) g_cand[(b0 + sel[e]) * CAP + p] = key[e];
        }
    }
}

// ---------------------------------------------------------------------------
// Pass 2: one block per batch.
//   keys (sigmoid_bits<<32 | ~idx) -> 2048-bin radix select (rank 300)
//   -> compact -> small bitonic sort -> decode boxes -> ballot IoU masks
//   -> serial greedy NMS (register-resident) -> outputs
// ---------------------------------------------------------------------------
extern __shared__ ull dynsm[];   // [CAP] skeys + [FCAP] cand2

__device__ __forceinline__ void bitonic_desc(ull* a, int N, int tid) {
    for (int k = 2; k <= N; k <<= 1) {
        for (int j = k >> 1; j > 0; j >>= 1) {
            for (int i = tid; i < N; i += 1024) {
                int ixj = i ^ j;
                if (ixj > i) {
                    ull a0 = a[i], a1 = a[ixj];
                    bool up = ((i & k) == 0);
                    if ((a0 < a1) == up) { a[i] = a1; a[ixj] = a0; }
                }
            }
            __syncthreads();
        }
    }
}

__global__ void __launch_bounds__(1024, 1)
k_select(const float* __restrict__ p_loc,
         const float* __restrict__ anchors,
         float* __restrict__ out) {
    __shared__ unsigned hist[NBINS];
    __shared__ unsigned wsum[32];
    __shared__ int sT, scount2;
    __shared__ float sx1[NK], sy1[NK], sx2[NK], sy2[NK], ssc[NK], sarea[NK];
    __shared__ unsigned smask[NK * NW];
    __shared__ unsigned svalid[NW];
    __shared__ unsigned srem[NW];

    ull* skeys = dynsm;
    ull* cand2 = dynsm + CAP;

    const int b = blockIdx.x;
    const int tid = threadIdx.x;

    int count = g_count[b];
    if (count > CAP) count = CAP;

    // Build exact keys: precise sigmoid on survivors only (conf carried in record).
    for (int i = tid; i < count; i += 1024) {
        ull c = g_cand[b * CAP + i];
        float x = __uint_as_float((unsigned)(c >> 32));
        unsigned a = (unsigned)(c & 0xFFFFFFFFu);
        float s = 1.0f / (1.0f + expf(-x));
        skeys[i] = ((ull)__float_as_uint(s) << 32) |
                   (ull)(0xFFFFFFFFu - a);         // tie-break: lower idx wins
    }
    for (int i = tid; i < NBINS; i += 1024) hist[i] = 0;
    if (tid == 0) { sT = 0; scount2 = 0; }
    if (tid < NW) svalid[tid] = 0u;
    __syncthreads();

    // Histogram over sigmoid mantissa bits [23:12] (all scores in [0.5,1], shared exponent).
    for (int i = tid; i < count; i += 1024) {
        unsigned hi = (unsigned)(skeys[i] >> 32);
        int bin = min((int)((hi >> 12) - 0x3F000u), NBINS - 1);
        atomicAdd(&hist[bin], 1u);
    }
    __syncthreads();

    // Block suffix scan (2 bins/thread, reverse order) to find rank-NK bin.
    {
        int r0 = 2 * tid, r1 = 2 * tid + 1;
        unsigned h0 = hist[NBINS - 1 - r0];
        unsigned h1 = hist[NBINS - 1 - r1];
        unsigned tsum = h0 + h1;
        unsigned lane = tid & 31, wid = tid >> 5;
        unsigned inc = tsum;
        #pragma unroll
        for (int o = 1; o < 32; o <<= 1) {
            unsigned n = __shfl_up_sync(FULLM, inc, o);
            if (lane >= (unsigned)o) inc += n;
        }
        if (lane == 31) wsum[wid] = inc;
        __syncthreads();
        if (tid < 32) {
            unsigned w = wsum[tid];
            #pragma unroll
            for (int o = 1; o < 32; o <<= 1) {
                unsigned n = __shfl_up_sync(FULLM, w, o);
                if (tid >= (unsigned)o) w += n;
            }
            wsum[tid] = w;
        }
        __syncthreads();
        unsigned C0 = (wid ? wsum[wid - 1] : 0u) + (inc - tsum);
        unsigned C1 = C0 + h0;
        if (C0 < NK && C0 + h0 >= NK) sT = NBINS - 1 - r0;
        if (C1 < NK && C1 + h1 >= NK) sT = NBINS - 1 - r1;
    }
    __syncthreads();

    // Compact bin >= T.
    int T = sT;
    for (int i = tid; i < count; i += 1024) {
        unsigned hi = (unsigned)(skeys[i] >> 32);
        int bin = min((int)((hi >> 12) - 0x3F000u), NBINS - 1);
        if (bin >= T) {
            int p = atomicAdd(&scount2, 1);
            if (p < FCAP) cand2[p] = skeys[i];
        }
    }
    __syncthreads();
    int count2 = scount2;

    const ull* top;
    int len;
    if (count2 <= FCAP) {
        int N2 = 512;
        while (N2 < count2) N2 <<= 1;
        for (int i = tid; i < N2; i += 1024)
            if (i >= count2) cand2[i] = 0ULL;
        __syncthreads();
        bitonic_desc(cand2, N2, tid);
        top = cand2;
        len = count2 < NK ? count2 : NK;
    } else {
        // Pathological tie pile-up: full sort fallback.
        int N = 512;
        while (N < count) N <<= 1;
        for (int i = tid; i < N; i += 1024)
            if (i >= count) skeys[i] = 0ULL;
        __syncthreads();
        bitonic_desc(skeys, N, tid);
        top = skeys;
        len = count < NK ? count : NK;
    }

    // Decode boxes for top-K slots.
    if (tid < NK) {
        ull key = (tid < len) ? top[tid] : 0ULL;
        float s = __uint_as_float((unsigned)(key >> 32));
        bool valid = (tid < len) && (s >= 0.5f);
        float x1 = 0.f, y1 = 0.f, x2 = 0.f, y2 = 0.f, area = 0.f;
        if (valid) {
            int a = (int)(0xFFFFFFFFu - (unsigned)(key & 0xFFFFFFFFu));
            float4 an = ((const float4*)anchors)[a];
            float4 lv = ((const float4*)p_loc)[(size_t)b * NA + a];
            float cx = an.x + lv.x * 0.1f * an.z;
            float cy = an.y + lv.y * 0.1f * an.w;
            float w = an.z * expf(lv.z * 0.2f);
            float h = an.w * expf(lv.w * 0.2f);
            x1 = cx - 0.5f * w; y1 = cy - 0.5f * h;
            x2 = cx + 0.5f * w; y2 = cy + 0.5f * h;
            area = fmaxf(x2 - x1, 0.f) * fmaxf(y2 - y1, 0.f);
            atomicOr(&svalid[tid >> 5], 1u << (tid & 31));
        }
        sx1[tid] = x1; sy1[tid] = y1; sx2[tid] = x2; sy2[tid] = y2;
        ssc[tid] = s; sarea[tid] = area;
    }
    __syncthreads();

    // Suppression masks via ballot: warp (w,c) keeps its 32 j-boxes in registers,
    // loops i over a 100-wide chunk with broadcast LDS. smask[i][w] bit j set
    // iff (j>i && iou(i,j)>0.3).
    {
        int warpId = tid >> 5, lane = tid & 31;
        if (warpId < 30) {
            int w = warpId % NW;          // mask word
            int c = warpId / NW;          // i-chunk (0..2), 100 each
            int j = w * 32 + lane;
            bool jv = (j < NK);
            int js = jv ? j : 0;
            float jx1 = sx1[js], jy1 = sy1[js], jx2 = sx2[js], jy2 = sy2[js], ja = sarea[js];
            int i0 = c * 100, i1 = i0 + 100;
            for (int i = i0; i < i1; i++) {
                float lt0 = fmaxf(sx1[i], jx1), lt1 = fmaxf(sy1[i], jy1);
                float rb0 = fminf(sx2[i], jx2), rb1 = fminf(sy2[i], jy2);
                float iw = fmaxf(rb0 - lt0, 0.f), ih = fmaxf(rb1 - lt1, 0.f);
                float inter = iw * ih;
                float uni = fmaxf(sarea[i] + ja - inter, 1e-9f);
                bool sup = jv && (j > i) && (inter > 0.3f * uni);
                unsigned m = __ballot_sync(FULLM, sup);
                if (lane == 0) smask[i * NW + w] = m;
            }
        }
    }
    __syncthreads();

    // Serial greedy NMS on one thread; rem[] statically indexed in registers.
    if (tid == 0) {
        unsigned rem[NW];
        #pragma unroll
        for (int w = 0; w < NW; w++) rem[w] = ~svalid[w];
        #pragma unroll
        for (int w = 0; w < NW; w++) {
            int nbit = (w == NW - 1) ? (NK - 32 * (NW - 1)) : 32;
            for (int bit = 0; bit < nbit; bit++) {
                if (!((rem[w] >> bit) & 1u)) {       // keep -> apply its mask
                    const unsigned* mrow = &smask[(w * 32 + bit) * NW];
                    #pragma unroll
                    for (int k = 0; k < NW; k++) rem[k] |= mrow[k];
                }
            }
        }
        #pragma unroll
        for (int w = 0; w < NW; w++) srem[w] = rem[w];
    }
    __syncthreads();

    // Outputs: [ids(4800) | boxes(19200) | labels(4800) | scores(4800) | keep(4800)]
    if (tid < NK) {
        bool keep = !((srem[tid >> 5] >> (tid & 31)) & 1u);
        int slot = b * NK + tid;
        float kf = keep ? 1.0f : 0.0f;
        out[slot] = keep ? (float)b : -1.0f;
        float* ob = out + NB * NK + slot * 4;
        ob[0] = sx1[tid] * kf;
        ob[1] = sy1[tid] * kf;
        ob[2] = sx2[tid] * kf;
        ob[3] = sy2[tid] * kf;
        out[NB * NK * 5 + slot] = kf;
        out[NB * NK * 6 + slot] = ssc[tid] * kf;
        out[NB * NK * 7 + slot] = kf;
    }

    // Reset counter for next graph replay (module-load value is also 0).
    if (tid == 0) g_count[b] = 0;
}

extern "C" void kernel_launch(void* const* d_in, const int* in_sizes, int n_in,
                              void* d_out, int out_size) {
    const float* p_loc   = (const float*)d_in[0];
    const float* p_conf  = (const float*)d_in[1];
    // d_in[2] = p_landms: dead compute in reference, intentionally unread.
    const float* anchors = (const float*)d_in[3];
    float* out = (float*)d_out;

    static int smem_set = 0;
    if (!smem_set) {
        cudaFuncSetAttribute(k_select, cudaFuncAttributeMaxDynamicSharedMemorySize,
                             (CAP + FCAP) * (int)sizeof(ull));
        smem_set = 1;
    }

    k_scan<<<(NB * NA / 4) / 256, 256>>>((const float4*)p_conf);
    k_select<<<NB, 1024, (CAP + FCAP) * sizeof(ull)>>>(p_loc, anchors, out);
}

// round 5
// speedup vs baseline: 5.3821x; 1.6179x over previous
#include <cuda_runtime.h>
#include <cstdint>

#define NB 16
#define NA 200000
#define NK 300
#define CAP 16384
#define FCAP 2048
#define NW 10          // ceil(300/32) mask words
#define NBINS 2048
#define FULLM 0xffffffffu

typedef unsigned long long ull;

// Scratch (no allocations allowed). g_cand holds FINAL sort keys:
// (sigmoid_bits << 32) | (0xFFFFFFFF - anchor_idx)  -> desc sort == (score desc, idx asc).
__device__ int g_count[NB];          // zero-init at load; k_select re-zeroes each replay
__device__ ull g_cand[NB * CAP];

// ---------------------------------------------------------------------------
// Pass 1: streaming scan of p_conf (12.8 MB). sigmoid(x)>=0.5 <=> x>=0.
// Precise sigmoid only for the ~2.3% positives (hidden under DRAM latency).
// Block-aggregated append: one global atomicAdd per (block, batch).
// ---------------------------------------------------------------------------
__global__ void k_scan(const float4* __restrict__ conf4) {
    __shared__ int scnt[2];
    __shared__ int sbase[2];
    const int t = threadIdx.x;
    if (t < 2) scnt[t] = 0;
    __syncthreads();

    int gi = blockIdx.x * 256 + t;           // float4 index (grid exact: 800000)
    float4 v = conf4[gi];
    int e0 = gi * 4;
    int b0 = (blockIdx.x * 1024) / NA;       // batch of first elem in block
    int split = (b0 + 1) * NA;               // first elem of next batch

    ull key[4]; int pos[4]; int sel[4]; bool pred[4];
    float xs[4] = {v.x, v.y, v.z, v.w};
    #pragma unroll
    for (int e = 0; e < 4; e++) {
        pred[e] = (xs[e] >= 0.0f);
        if (pred[e]) {
            int idx = e0 + e;
            sel[e] = (idx >= split) ? 1 : 0;
            unsigned a = (unsigned)(idx - (b0 + sel[e]) * NA);
            float s = 1.0f / (1.0f + expf(-xs[e]));
            key[e] = ((ull)__float_as_uint(s) << 32) | (ull)(0xFFFFFFFFu - a);
            pos[e] = atomicAdd(&scnt[sel[e]], 1);
        }
    }
    __syncthreads();
    if (t < 2) sbase[t] = scnt[t] ? atomicAdd(&g_count[b0 + t], scnt[t]) : 0;
    __syncthreads();
    #pragma unroll
    for (int e = 0; e < 4; e++) {
        if (pred[e]) {
            int p = sbase[sel[e]] + pos[e];
            if (p < CAP) g_cand[(b0 + sel[e]) * CAP + p] = key[e];
        }
    }
}

// ---------------------------------------------------------------------------
// Pass 2: one block per batch.
//   2048-bin radix select (rank 300) -> ballot compact -> counting-rank sort
//   -> decode boxes -> transpose (suppressor) IoU masks via ballot
//   -> parallel fixed-point greedy NMS -> outputs
// All shared memory static (~46.4 KB) -> fits default 48 KB, no attribute call.
// ---------------------------------------------------------------------------
__device__ __forceinline__ void bitonic_desc(ull* a, int N, int tid) {
    for (int k = 2; k <= N; k <<= 1) {
        for (int j = k >> 1; j > 0; j >>= 1) {
            for (int i = tid; i < N; i += 1024) {
                int ixj = i ^ j;
                if (ixj > i) {
                    ull a0 = a[i], a1 = a[ixj];
                    bool up = ((i & k) == 0);
                    if ((a0 < a1) == up) { a[i] = a1; a[ixj] = a0; }
                }
            }
            __syncthreads();
        }
    }
}

__device__ __forceinline__ int key_bin(unsigned hi) {
    return min((int)((hi >> 12) - 0x3F000u), NBINS - 1);
}

__global__ void __launch_bounds__(1024, 1)
k_select(const float* __restrict__ p_loc,
         const float* __restrict__ anchors,
         float* __restrict__ out) {
    __shared__ unsigned hist[NBINS];            // 8 KB
    __shared__ ull cand2[FCAP];                 // 16 KB
    __shared__ unsigned wsum[32];
    __shared__ int sT, scount2, schanged;
    __shared__ ull sstage[NK];                  // 2.4 KB
    __shared__ float sx1[NK], sy1[NK], sx2[NK], sy2[NK], ssc[NK], sarea[NK];  // 7.2 KB
    __shared__ unsigned colmask[NK * NW];       // 12 KB; colmask[j][w] bit i: i<j && iou>thr
    __shared__ unsigned svalid[NW];
    __shared__ unsigned kw[2][NW];

    const int b = blockIdx.x;
    const int tid = threadIdx.x;
    const int lane = tid & 31;
    const int wrp = tid >> 5;
    const unsigned ltm = (1u << lane) - 1u;

    int count = g_count[b];
    if (count > CAP) count = CAP;

    // Init.
    for (int i = tid; i < NBINS; i += 1024) hist[i] = 0;
    if (tid < NK) sstage[tid] = 0ULL;
    if (tid == 0) { sT = 0; scount2 = 0; }
    __syncthreads();

    // Histogram over sigmoid mantissa bits [23:12] (scores share the [0.5,1) exponent).
    for (int i = tid; i < count; i += 1024) {
        unsigned hi = (unsigned)(g_cand[b * CAP + i] >> 32);
        atomicAdd(&hist[key_bin(hi)], 1u);
    }
    __syncthreads();

    // Block suffix scan (2 bins/thread, reverse order) to find the rank-NK bin.
    {
        int r0 = 2 * tid, r1 = 2 * tid + 1;
        unsigned h0 = hist[NBINS - 1 - r0];
        unsigned h1 = hist[NBINS - 1 - r1];
        unsigned tsum = h0 + h1;
        unsigned inc = tsum;
        #pragma unroll
        for (int o = 1; o < 32; o <<= 1) {
            unsigned n = __shfl_up_sync(FULLM, inc, o);
            if (lane >= o) inc += n;
        }
        if (lane == 31) wsum[wrp] = inc;
        __syncthreads();
        if (tid < 32) {
            unsigned w = wsum[tid];
            #pragma unroll
            for (int o = 1; o < 32; o <<= 1) {
                unsigned n = __shfl_up_sync(FULLM, w, o);
                if (tid >= o) w += n;
            }
            wsum[tid] = w;
        }
        __syncthreads();
        unsigned C0 = (wrp ? wsum[wrp - 1] : 0u) + (inc - tsum);
        unsigned C1 = C0 + h0;
        if (C0 < NK && C0 + h0 >= NK) sT = NBINS - 1 - r0;
        if (C1 < NK && C1 + h1 >= NK) sT = NBINS - 1 - r1;
    }
    __syncthreads();

    // Compact bin >= T with warp-aggregated atomics (padded loop -> full-warp ballots).
    {
        int T = sT;
        int countP = (count + 1023) & ~1023;
        for (int i = tid; i < countP; i += 1024) {
            ull k = 0; bool pred = false;
            if (i < count) {
                k = g_cand[b * CAP + i];
                pred = (key_bin((unsigned)(k >> 32)) >= T);
            }
            unsigned m = __ballot_sync(FULLM, pred);
            if (pred) {
                int leader = __ffs(m) - 1;
                int base = 0;
                if (lane == leader) base = atomicAdd(&scount2, __popc(m));
                base = __shfl_sync(m, base, leader);
                int p = base + __popc(m & ltm);
                if (p < FCAP) cand2[p] = k;
            }
        }
    }
    __syncthreads();
    int count2 = min(scount2, FCAP);

    // Sort: counting-rank (keys unique by construction) for count2 <= 1024; bitonic else.
    if (count2 <= 1024) {
        if (tid < count2) {
            ull my = cand2[tid];
            int r = 0;
            int j = 0;
            for (; j + 4 <= count2; j += 4) {
                r += (cand2[j] > my) + (cand2[j + 1] > my)
                   + (cand2[j + 2] > my) + (cand2[j + 3] > my);
            }
            for (; j < count2; j++) r += (cand2[j] > my);
            if (r < NK) sstage[r] = my;
        }
        __syncthreads();
    } else {
        int N2 = 2048;                          // count2 <= FCAP == 2048
        for (int i = count2 + tid; i < N2; i += 1024) cand2[i] = 0ULL;
        __syncthreads();
        bitonic_desc(cand2, N2, tid);
        if (tid < NK) sstage[tid] = cand2[tid];
        __syncthreads();
    }

    // Decode boxes for top-K slots; build svalid via ballot.
    {
        bool valid = false;
        float x1 = 0.f, y1 = 0.f, x2 = 0.f, y2 = 0.f, s = 0.f, area = 0.f;
        if (tid < NK) {
            ull key = sstage[tid];
            s = __uint_as_float((unsigned)(key >> 32));
            valid = (key != 0ULL);              // real keys have s >= 0.5
            if (valid) {
                int a = (int)(0xFFFFFFFFu - (unsigned)(key & 0xFFFFFFFFu));
                float4 an = ((const float4*)anchors)[a];
                float4 lv = ((const float4*)p_loc)[(size_t)b * NA + a];
                float cx = an.x + lv.x * 0.1f * an.z;
                float cy = an.y + lv.y * 0.1f * an.w;
                float w = an.z * expf(lv.z * 0.2f);
                float h = an.w * expf(lv.w * 0.2f);
                x1 = cx - 0.5f * w; y1 = cy - 0.5f * h;
                x2 = cx + 0.5f * w; y2 = cy + 0.5f * h;
                area = fmaxf(x2 - x1, 0.f) * fmaxf(y2 - y1, 0.f);
            }
        }
        unsigned vb = __ballot_sync(FULLM, valid);
        if (lane == 0 && wrp < NW) svalid[wrp] = vb;
        if (tid < NK) {
            sx1[tid] = x1; sy1[tid] = y1; sx2[tid] = x2; sy2[tid] = y2;
            ssc[tid] = s; sarea[tid] = area;
        }
    }
    __syncthreads();

    // Suppressor (transpose) masks via ballot: warp (wi,c) holds 32 i-boxes in
    // registers; loops j over a 100-chunk with broadcast LDS.
    {
        if (wrp < 30) {
            int wi = wrp % NW;                  // i-word
            int c = wrp / NW;                   // j-chunk (0..2)
            int i = wi * 32 + lane;
            bool iv = (i < NK);
            int is = iv ? i : 0;
            float ix1 = sx1[is], iy1 = sy1[is], ix2 = sx2[is], iy2 = sy2[is], ia = sarea[is];
            int j0 = c * 100, j1 = j0 + 100;
            for (int j = j0; j < j1; j++) {
                float lt0 = fmaxf(ix1, sx1[j]), lt1 = fmaxf(iy1, sy1[j]);
                float rb0 = fminf(ix2, sx2[j]), rb1 = fminf(iy2, sy2[j]);
                float iw = fmaxf(rb0 - lt0, 0.f), ih = fmaxf(rb1 - lt1, 0.f);
                float inter = iw * ih;
                float uni = fmaxf(ia + sarea[j] - inter, 1e-9f);
                bool sup = iv && (i < j) && (inter > 0.3f * uni);
                unsigned m = __ballot_sync(FULLM, sup);
                if (lane == 0) colmask[j * NW + wi] = m;
            }
        }
    }
    __syncthreads();

    // Parallel greedy NMS: iterate keep[j] = valid[j] & !exists(i<j kept, sup(i,j)).
    // Greedy is the UNIQUE fixed point (induction on j); element j stabilizes once
    // all i<j have -> <= NK iters; typically 2-4 for sparse random boxes.
    {
        if (tid < NW) kw[0][tid] = svalid[tid];
        __syncthreads();
        int cur = 0;
        bool myvalid = (tid < NK) && ((svalid[tid >> 5] >> (tid & 31)) & 1u);
        for (int t = 0; t < NK + 2; t++) {
            if (tid == 0) schanged = 0;
            __syncthreads();
            bool kp = false;
            if (tid < NK) {
                unsigned sup = 0;
                #pragma unroll
                for (int w = 0; w < NW; w++) sup |= colmask[tid * NW + w] & kw[cur][w];
                kp = myvalid && (sup == 0);
            }
            unsigned word = __ballot_sync(FULLM, kp);
            if (lane == 0 && wrp < NW) {
                kw[cur ^ 1][wrp] = word;
                if (word != kw[cur][wrp]) schanged = 1;
            }
            __syncthreads();
            if (!schanged) break;               // fixed point reached == greedy result
            cur ^= 1;
        }
        if (tid < NW) svalid[tid] = kw[cur][tid];   // final keep words
    }
    __syncthreads();

    // Outputs: [ids(4800) | boxes(19200) | labels(4800) | scores(4800) | keep(4800)]
    if (tid < NK) {
        bool keep = (svalid[tid >> 5] >> (tid & 31)) & 1u;
        int slot = b * NK + tid;
        float kf = keep ? 1.0f : 0.0f;
        out[slot] = keep ? (float)b : -1.0f;
        float* ob = out + NB * NK + slot * 4;
        ob[0] = sx1[tid] * kf;
        ob[1] = sy1[tid] * kf;
        ob[2] = sx2[tid] * kf;
        ob[3] = sy2[tid] * kf;
        out[NB * NK * 5 + slot] = kf;
        out[NB * NK * 6 + slot] = ssc[tid] * kf;
        out[NB * NK * 7 + slot] = kf;
    }

    // Reset counter for next graph replay (module-load value is also 0).
    if (tid == 0) g_count[b] = 0;
}

extern "C" void kernel_launch(void* const* d_in, const int* in_sizes, int n_in,
                              void* d_out, int out_size) {
    const float* p_loc   = (const float*)d_in[0];
    const float* p_conf  = (const float*)d_in[1];
    // d_in[2] = p_landms: dead compute in reference, intentionally unread.
    const float* anchors = (const float*)d_in[3];
    float* out = (float*)d_out;

    k_scan<<<(NB * NA / 4) / 256, 256>>>((const float4*)p_conf);
    k_select<<<NB, 1024>>>(p_loc, anchors, out);
}

// round 6
// speedup vs baseline: 6.5404x; 1.2152x over previous
#include <cuda_runtime.h>
#include <cstdint>

#define NB 16
#define NA 200000
#define NK 300
#define NKP 320        // padded box array (lane reads up to wi*32+31 = 319)
#define CAP 16384
#define FCAP 2048
#define NW 10          // ceil(300/32) mask words
#define NBINS 2048
#define FULLM 0xffffffffu

typedef unsigned long long ull;

// Scratch (no allocations allowed). g_cand holds FINAL sort keys:
// (sigmoid_bits << 32) | (0xFFFFFFFF - anchor_idx)  -> desc sort == (score desc, idx asc).
__device__ int g_count[NB];          // zero-init at load; k_select re-zeroes each replay
__device__ ull g_cand[NB * CAP];

// ---------------------------------------------------------------------------
// Pass 1: streaming scan of p_conf (12.8 MB). sigmoid(x)>=0.5 <=> x>=0.
// Precise sigmoid only for the ~2.3% positives. One global atomicAdd per
// (block, batch).
// ---------------------------------------------------------------------------
__global__ void k_scan(const float4* __restrict__ conf4) {
    __shared__ int scnt[2];
    __shared__ int sbase[2];
    const int t = threadIdx.x;
    if (t < 2) scnt[t] = 0;
    __syncthreads();

    int gi = blockIdx.x * 256 + t;           // float4 index (grid exact: 800000)
    float4 v = conf4[gi];
    int e0 = gi * 4;
    int b0 = (blockIdx.x * 1024) / NA;       // batch of first elem in block
    int split = (b0 + 1) * NA;               // first elem of next batch

    ull key[4]; int pos[4]; int sel[4]; bool pred[4];
    float xs[4] = {v.x, v.y, v.z, v.w};
    #pragma unroll
    for (int e = 0; e < 4; e++) {
        pred[e] = (xs[e] >= 0.0f);
        if (pred[e]) {
            int idx = e0 + e;
            sel[e] = (idx >= split) ? 1 : 0;
            unsigned a = (unsigned)(idx - (b0 + sel[e]) * NA);
            float s = 1.0f / (1.0f + expf(-xs[e]));
            key[e] = ((ull)__float_as_uint(s) << 32) | (ull)(0xFFFFFFFFu - a);
            pos[e] = atomicAdd(&scnt[sel[e]], 1);
        }
    }
    __syncthreads();
    if (t < 2) sbase[t] = scnt[t] ? atomicAdd(&g_count[b0 + t], scnt[t]) : 0;
    __syncthreads();
    #pragma unroll
    for (int e = 0; e < 4; e++) {
        if (pred[e]) {
            int p = sbase[sel[e]] + pos[e];
            if (p < CAP) g_cand[(b0 + sel[e]) * CAP + p] = key[e];
        }
    }
}

// ---------------------------------------------------------------------------
// Pass 2: one block per batch.
//   2048-bin radix select (rank 300) -> ballot compact -> counting-rank sort
//   -> decode boxes -> TRIANGULAR suppressor IoU masks via ballot
//   -> parallel fixed-point greedy NMS -> outputs
// All shared memory static (~47 KB) -> fits default 48 KB limit.
// ---------------------------------------------------------------------------
__device__ __forceinline__ void bitonic_desc(ull* a, int N, int tid) {
    for (int k = 2; k <= N; k <<= 1) {
        for (int j = k >> 1; j > 0; j >>= 1) {
            for (int i = tid; i < N; i += 1024) {
                int ixj = i ^ j;
                if (ixj > i) {
                    ull a0 = a[i], a1 = a[ixj];
                    bool up = ((i & k) == 0);
                    if ((a0 < a1) == up) { a[i] = a1; a[ixj] = a0; }
                }
            }
            __syncthreads();
        }
    }
}

__device__ __forceinline__ int key_bin(unsigned hi) {
    return min((int)((hi >> 12) - 0x3F000u), NBINS - 1);
}

__global__ void __launch_bounds__(1024, 1)
k_select(const float* __restrict__ p_loc,
         const float* __restrict__ anchors,
         float* __restrict__ out) {
    __shared__ unsigned hist[NBINS];            // 8 KB
    __shared__ ull cand2[FCAP];                 // 16 KB
    __shared__ unsigned wsum[32];
    __shared__ int sT, scount2, schanged;
    __shared__ ull sstage[NK];                  // 2.4 KB
    __shared__ float4 sbox[NKP];                // 5.12 KB (x1,y1,x2,y2)
    __shared__ float sarea[NKP];                // 1.28 KB
    __shared__ float ssc[NK];                   // 1.2 KB
    __shared__ unsigned colmask[NK * NW];       // 12 KB; colmask[j][w] bit i: i<j && iou>thr
    __shared__ unsigned svalid[NW];
    __shared__ unsigned kw[2][NW];

    const int b = blockIdx.x;
    const int tid = threadIdx.x;
    const int lane = tid & 31;
    const int wrp = tid >> 5;
    const unsigned ltm = (1u << lane) - 1u;

    int count = g_count[b];
    if (count > CAP) count = CAP;

    // Init: hist, colmask, sstage, pad boxes.
    for (int i = tid; i < NBINS; i += 1024) hist[i] = 0;
    for (int i = tid; i < NK * NW; i += 1024) colmask[i] = 0;
    if (tid < NK) sstage[tid] = 0ULL;
    if (tid >= NK && tid < NKP) {               // pad entries 300..319
        sbox[tid] = make_float4(0.f, 0.f, 0.f, 0.f);
        sarea[tid] = 0.f;
    }
    if (tid == 0) { sT = 0; scount2 = 0; }
    __syncthreads();

    // Histogram over sigmoid mantissa bits [23:12] (scores share the [0.5,1) exponent).
    for (int i = tid; i < count; i += 1024) {
        unsigned hi = (unsigned)(g_cand[b * CAP + i] >> 32);
        atomicAdd(&hist[key_bin(hi)], 1u);
    }
    __syncthreads();

    // Block suffix scan (2 bins/thread, reverse order) to find the rank-NK bin.
    {
        int r0 = 2 * tid, r1 = 2 * tid + 1;
        unsigned h0 = hist[NBINS - 1 - r0];
        unsigned h1 = hist[NBINS - 1 - r1];
        unsigned tsum = h0 + h1;
        unsigned inc = tsum;
        #pragma unroll
        for (int o = 1; o < 32; o <<= 1) {
            unsigned n = __shfl_up_sync(FULLM, inc, o);
            if (lane >= o) inc += n;
        }
        if (lane == 31) wsum[wrp] = inc;
        __syncthreads();
        if (tid < 32) {
            unsigned w = wsum[tid];
            #pragma unroll
            for (int o = 1; o < 32; o <<= 1) {
                unsigned n = __shfl_up_sync(FULLM, w, o);
                if (tid >= o) w += n;
            }
            wsum[tid] = w;
        }
        __syncthreads();
        unsigned C0 = (wrp ? wsum[wrp - 1] : 0u) + (inc - tsum);
        unsigned C1 = C0 + h0;
        if (C0 < NK && C0 + h0 >= NK) sT = NBINS - 1 - r0;
        if (C1 < NK && C1 + h1 >= NK) sT = NBINS - 1 - r1;
    }
    __syncthreads();

    // Compact bin >= T with warp-aggregated atomics.
    {
        int T = sT;
        int countP = (count + 1023) & ~1023;
        for (int i = tid; i < countP; i += 1024) {
            ull k = 0; bool pred = false;
            if (i < count) {
                k = g_cand[b * CAP + i];
                pred = (key_bin((unsigned)(k >> 32)) >= T);
            }
            unsigned m = __ballot_sync(FULLM, pred);
            if (pred) {
                int leader = __ffs(m) - 1;
                int base = 0;
                if (lane == leader) base = atomicAdd(&scount2, __popc(m));
                base = __shfl_sync(m, base, leader);
                int p = base + __popc(m & ltm);
                if (p < FCAP) cand2[p] = k;
            }
        }
    }
    __syncthreads();
    int count2 = min(scount2, FCAP);

    // Sort: counting-rank (keys unique by construction) for count2 <= 1024; bitonic else.
    if (count2 <= 1024) {
        if (tid < count2) {
            ull my = cand2[tid];
            int r = 0;
            int j = 0;
            for (; j + 4 <= count2; j += 4) {
                r += (cand2[j] > my) + (cand2[j + 1] > my)
                   + (cand2[j + 2] > my) + (cand2[j + 3] > my);
            }
            for (; j < count2; j++) r += (cand2[j] > my);
            if (r < NK) sstage[r] = my;
        }
        __syncthreads();
    } else {
        int N2 = 2048;                          // count2 <= FCAP == 2048
        for (int i = count2 + tid; i < N2; i += 1024) cand2[i] = 0ULL;
        __syncthreads();
        bitonic_desc(cand2, N2, tid);
        if (tid < NK) sstage[tid] = cand2[tid];
        __syncthreads();
    }

    // Decode boxes for top-K slots; build svalid via ballot.
    {
        bool valid = false;
        float x1 = 0.f, y1 = 0.f, x2 = 0.f, y2 = 0.f, s = 0.f, area = 0.f;
        if (tid < NK) {
            ull key = sstage[tid];
            s = __uint_as_float((unsigned)(key >> 32));
            valid = (key != 0ULL);              // real keys have s >= 0.5
            if (valid) {
                int a = (int)(0xFFFFFFFFu - (unsigned)(key & 0xFFFFFFFFu));
                float4 an = ((const float4*)anchors)[a];
                float4 lv = ((const float4*)p_loc)[(size_t)b * NA + a];
                float cx = an.x + lv.x * 0.1f * an.z;
                float cy = an.y + lv.y * 0.1f * an.w;
                float w = an.z * expf(lv.z * 0.2f);
                float h = an.w * expf(lv.w * 0.2f);
                x1 = cx - 0.5f * w; y1 = cy - 0.5f * h;
                x2 = cx + 0.5f * w; y2 = cy + 0.5f * h;
                area = fmaxf(x2 - x1, 0.f) * fmaxf(y2 - y1, 0.f);
            }
        }
        unsigned vb = __ballot_sync(FULLM, valid);
        if (lane == 0 && wrp < NW) svalid[wrp] = vb;
        if (tid < NK) {
            sbox[tid] = make_float4(x1, y1, x2, y2);
            sarea[tid] = area;
            ssc[tid] = s;
        }
    }
    __syncthreads();

    // Triangular suppressor masks: warp handles rows j = wrp, wrp+32, ...
    // Only words wi <= j>>5 can contain suppressors (i < j). j-box in registers
    // (broadcast LDS), i-boxes via one LDS.128 + LDS.32 per inner iteration.
    for (int j = wrp; j < NK; j += 32) {
        float4 bj = sbox[j];
        float ja = sarea[j];
        int wmax = j >> 5;
        for (int wi = 0; wi <= wmax; wi++) {
            int i = wi * 32 + lane;              // <= 319, in padded range
            float4 bi = sbox[i];
            float lt0 = fmaxf(bi.x, bj.x), lt1 = fmaxf(bi.y, bj.y);
            float rb0 = fminf(bi.z, bj.z), rb1 = fminf(bi.w, bj.w);
            float iw = fmaxf(rb0 - lt0, 0.f), ih = fmaxf(rb1 - lt1, 0.f);
            float inter = iw * ih;
            float uni = fmaxf(sarea[i] + ja - inter, 1e-9f);
            bool sup = (i < j) && (inter > 0.3f * uni);
            unsigned m = __ballot_sync(FULLM, sup);
            if (lane == 0) colmask[j * NW + wi] = m;
        }
    }
    __syncthreads();

    // Parallel greedy NMS: iterate keep[j] = valid[j] & !exists(i<j kept, sup(i,j)).
    // Greedy is the unique fixed point; converges in chain-depth iterations.
    {
        if (tid < NW) kw[0][tid] = svalid[tid];
        __syncthreads();
        int cur = 0;
        bool myvalid = (tid < NK) && ((svalid[tid >> 5] >> (tid & 31)) & 1u);
        for (int t = 0; t < NK + 2; t++) {
            if (tid == 0) schanged = 0;
            __syncthreads();
            bool kp = false;
            if (tid < NK) {
                unsigned sup = 0;
                #pragma unroll
                for (int w = 0; w < NW; w++) sup |= colmask[tid * NW + w] & kw[cur][w];
                kp = myvalid && (sup == 0);
            }
            unsigned word = __ballot_sync(FULLM, kp);
            if (lane == 0 && wrp < NW) {
                kw[cur ^ 1][wrp] = word;
                if (word != kw[cur][wrp]) schanged = 1;
            }
            __syncthreads();
            if (!schanged) break;               // fixed point == greedy result
            cur ^= 1;
        }
        if (tid < NW) svalid[tid] = kw[cur][tid];   // final keep words
    }
    __syncthreads();

    // Outputs: [ids(4800) | boxes(19200) | labels(4800) | scores(4800) | keep(4800)]
    if (tid < NK) {
        bool keep = (svalid[tid >> 5] >> (tid & 31)) & 1u;
        int slot = b * NK + tid;
        float kf = keep ? 1.0f : 0.0f;
        float4 bx = sbox[tid];
        out[slot] = keep ? (float)b : -1.0f;
        float* ob = out + NB * NK + slot * 4;
        ob[0] = bx.x * kf;
        ob[1] = bx.y * kf;
        ob[2] = bx.z * kf;
        ob[3] = bx.w * kf;
        out[NB * NK * 5 + slot] = kf;
        out[NB * NK * 6 + slot] = ssc[tid] * kf;
        out[NB * NK * 7 + slot] = kf;
    }

    // Reset counter for next graph replay (module-load value is also 0).
    if (tid == 0) g_count[b] = 0;
}

extern "C" void kernel_launch(void* const* d_in, const int* in_sizes, int n_in,
                              void* d_out, int out_size) {
    const float* p_loc   = (const float*)d_in[0];
    const float* p_conf  = (const float*)d_in[1];
    // d_in[2] = p_landms: dead compute in reference, intentionally unread.
    const float* anchors = (const float*)d_in[3];
    float* out = (float*)d_out;

    k_scan<<<(NB * NA / 4) / 256, 256>>>((const float4*)p_conf);
    k_select<<<NB, 1024>>>(p_loc, anchors, out);
}

// round 7
// speedup vs baseline: 6.5943x; 1.0083x over previous
#include <cuda_runtime.h>
#include <cstdint>

#define NB 16
#define NA 200000
#define NK 300
#define NKP 320        // padded box array (lane reads up to wi*32+31 = 319)
#define CAP 16384
#define FCAP 2048
#define NW 10          // ceil(300/32) mask words
#define NBINS 2048
#define FULLM 0xffffffffu

typedef unsigned long long ull;

// Scratch (no allocations allowed). g_cand holds FINAL sort keys:
// (sigmoid_bits << 32) | (0xFFFFFFFF - anchor_idx)  -> desc sort == (score desc, idx asc).
// g_hist: per-batch 2048-bin histogram of sigmoid mantissa bits [23:12].
// All zero-init at module load; k_select re-zeroes g_count/g_hist each replay.
__device__ int g_count[NB];
__device__ unsigned g_hist[NB][NBINS];
__device__ ull g_cand[NB * CAP];

__device__ __forceinline__ int bin_of(unsigned sbits) {
    return min((int)((sbits >> 12) - 0x3F000u), NBINS - 1);
}

// ---------------------------------------------------------------------------
// Pass 1: streaming scan of p_conf (12.8 MB). sigmoid(x)>=0.5 <=> x>=0.
// Precise sigmoid only for the ~2.3% positives. Also builds the per-batch
// score histogram with fire-and-forget global atomics (RED), spread over
// 3125 blocks. One compacting atomicAdd per (block, batch).
// ---------------------------------------------------------------------------
__global__ void k_scan(const float4* __restrict__ conf4) {
    __shared__ int scnt[2];
    __shared__ int sbase[2];
    const int t = threadIdx.x;
    if (t < 2) scnt[t] = 0;
    __syncthreads();

    int gi = blockIdx.x * 256 + t;           // float4 index (grid exact: 800000)
    float4 v = conf4[gi];
    int e0 = gi * 4;
    int b0 = (blockIdx.x * 1024) / NA;       // batch of first elem in block
    int split = (b0 + 1) * NA;               // first elem of next batch

    ull key[4]; int pos[4]; int sel[4]; bool pred[4];
    float xs[4] = {v.x, v.y, v.z, v.w};
    #pragma unroll
    for (int e = 0; e < 4; e++) {
        pred[e] = (xs[e] >= 0.0f);
        if (pred[e]) {
            int idx = e0 + e;
            sel[e] = (idx >= split) ? 1 : 0;
            unsigned a = (unsigned)(idx - (b0 + sel[e]) * NA);
            float s = 1.0f / (1.0f + expf(-xs[e]));
            unsigned sbits = __float_as_uint(s);
            key[e] = ((ull)sbits << 32) | (ull)(0xFFFFFFFFu - a);
            pos[e] = atomicAdd(&scnt[sel[e]], 1);
            atomicAdd(&g_hist[b0 + sel[e]][bin_of(sbits)], 1u);
        }
    }
    __syncthreads();
    if (t < 2) sbase[t] = scnt[t] ? atomicAdd(&g_count[b0 + t], scnt[t]) : 0;
    __syncthreads();
    #pragma unroll
    for (int e = 0; e < 4; e++) {
        if (pred[e]) {
            int p = sbase[sel[e]] + pos[e];
            if (p < CAP) g_cand[(b0 + sel[e]) * CAP + p] = key[e];
        }
    }
}

// ---------------------------------------------------------------------------
// Pass 2: one block per batch.
//   suffix-scan prebuilt histogram (rank 300) -> ballot compact ->
//   counting-rank sort (paired LDS.128) -> decode boxes ->
//   triangular suppressor IoU masks via ballot ->
//   parallel fixed-point greedy NMS (triangular AND) -> outputs
// Static shared ~39 KB.
// ---------------------------------------------------------------------------
__device__ __forceinline__ void bitonic_desc(ull* a, int N, int tid) {
    for (int k = 2; k <= N; k <<= 1) {
        for (int j = k >> 1; j > 0; j >>= 1) {
            for (int i = tid; i < N; i += 1024) {
                int ixj = i ^ j;
                if (ixj > i) {
                    ull a0 = a[i], a1 = a[ixj];
                    bool up = ((i & k) == 0);
                    if ((a0 < a1) == up) { a[i] = a1; a[ixj] = a0; }
                }
            }
            __syncthreads();
        }
    }
}

__global__ void __launch_bounds__(1024, 1)
k_select(const float* __restrict__ p_loc,
         const float* __restrict__ anchors,
         float* __restrict__ out) {
    __shared__ __align__(16) ull cand2[FCAP];   // 16 KB
    __shared__ unsigned wsum[32];
    __shared__ int sT, scount2, schanged;
    __shared__ ull sstage[NK];                  // 2.4 KB
    __shared__ float4 sbox[NKP];                // 5.12 KB
    __shared__ float sarea[NKP];                // 1.28 KB
    __shared__ float ssc[NK];                   // 1.2 KB
    __shared__ unsigned colmask[NK * NW];       // 12 KB (triangular part only written/read)
    __shared__ unsigned svalid[NW];
    __shared__ unsigned kw[2][NW];

    const int b = blockIdx.x;
    const int tid = threadIdx.x;
    const int lane = tid & 31;
    const int wrp = tid >> 5;
    const unsigned ltm = (1u << lane) - 1u;

    int count = g_count[b];
    if (count > CAP) count = CAP;

    if (tid < NK) sstage[tid] = 0ULL;
    if (tid >= NK && tid < NKP) {               // pad entries 300..319
        sbox[tid] = make_float4(0.f, 0.f, 0.f, 0.f);
        sarea[tid] = 0.f;
    }
    if (tid == 0) { sT = 0; scount2 = 0; }

    // Suffix scan over the prebuilt histogram (2 bins/thread, reverse order).
    {
        int r0 = 2 * tid, r1 = 2 * tid + 1;
        unsigned h0 = g_hist[b][NBINS - 1 - r0];
        unsigned h1 = g_hist[b][NBINS - 1 - r1];
        unsigned tsum = h0 + h1;
        unsigned inc = tsum;
        #pragma unroll
        for (int o = 1; o < 32; o <<= 1) {
            unsigned n = __shfl_up_sync(FULLM, inc, o);
            if (lane >= o) inc += n;
        }
        if (lane == 31) wsum[wrp] = inc;
        __syncthreads();
        if (tid < 32) {
            unsigned w = wsum[tid];
            #pragma unroll
            for (int o = 1; o < 32; o <<= 1) {
                unsigned n = __shfl_up_sync(FULLM, w, o);
                if (tid >= o) w += n;
            }
            wsum[tid] = w;
        }
        __syncthreads();
        unsigned C0 = (wrp ? wsum[wrp - 1] : 0u) + (inc - tsum);
        unsigned C1 = C0 + h0;
        if (C0 < NK && C0 + h0 >= NK) sT = NBINS - 1 - r0;
        if (C1 < NK && C1 + h1 >= NK) sT = NBINS - 1 - r1;
    }
    __syncthreads();

    // Compact bin >= T with warp-aggregated atomics.
    {
        int T = sT;
        int countP = (count + 1023) & ~1023;
        for (int i = tid; i < countP; i += 1024) {
            ull k = 0; bool pred = false;
            if (i < count) {
                k = g_cand[b * CAP + i];
                pred = (bin_of((unsigned)(k >> 32)) >= T);
            }
            unsigned m = __ballot_sync(FULLM, pred);
            if (pred) {
                int leader = __ffs(m) - 1;
                int base = 0;
                if (lane == leader) base = atomicAdd(&scount2, __popc(m));
                base = __shfl_sync(m, base, leader);
                int p = base + __popc(m & ltm);
                if (p < FCAP) cand2[p] = k;
            }
        }
    }
    __syncthreads();
    int count2 = min(scount2, FCAP);

    // Sort: counting-rank (keys unique by construction), 2 keys per LDS.128.
    if (count2 <= 1024) {
        if (tid < count2) {
            ull my = cand2[tid];
            const ulonglong2* c2 = (const ulonglong2*)cand2;
            int r = 0;
            int np = count2 >> 1;
            for (int p = 0; p < np; p++) {
                ulonglong2 kk = c2[p];
                r += (kk.x > my) + (kk.y > my);
            }
            if (count2 & 1) r += (cand2[count2 - 1] > my);
            if (r < NK) sstage[r] = my;
        }
        __syncthreads();
    } else {
        int N2 = 2048;                          // count2 <= FCAP == 2048
        for (int i = count2 + tid; i < N2; i += 1024) cand2[i] = 0ULL;
        __syncthreads();
        bitonic_desc(cand2, N2, tid);
        if (tid < NK) sstage[tid] = cand2[tid];
        __syncthreads();
    }

    // Decode boxes for top-K slots; build svalid via ballot.
    {
        bool valid = false;
        float x1 = 0.f, y1 = 0.f, x2 = 0.f, y2 = 0.f, s = 0.f, area = 0.f;
        if (tid < NK) {
            ull key = sstage[tid];
            s = __uint_as_float((unsigned)(key >> 32));
            valid = (key != 0ULL);              // real keys have s >= 0.5
            if (valid) {
                int a = (int)(0xFFFFFFFFu - (unsigned)(key & 0xFFFFFFFFu));
                float4 an = ((const float4*)anchors)[a];
                float4 lv = ((const float4*)p_loc)[(size_t)b * NA + a];
                float cx = an.x + lv.x * 0.1f * an.z;
                float cy = an.y + lv.y * 0.1f * an.w;
                float w = an.z * expf(lv.z * 0.2f);
                float h = an.w * expf(lv.w * 0.2f);
                x1 = cx - 0.5f * w; y1 = cy - 0.5f * h;
                x2 = cx + 0.5f * w; y2 = cy + 0.5f * h;
                area = fmaxf(x2 - x1, 0.f) * fmaxf(y2 - y1, 0.f);
            }
        }
        unsigned vb = __ballot_sync(FULLM, valid);
        if (lane == 0 && wrp < NW) svalid[wrp] = vb;
        if (tid < NK) {
            sbox[tid] = make_float4(x1, y1, x2, y2);
            sarea[tid] = area;
            ssc[tid] = s;
        }
    }
    __syncthreads();

    // Triangular suppressor masks: warp handles rows j = wrp, wrp+32, ...
    // Only words wi <= j>>5 can contain suppressors (i < j).
    for (int j = wrp; j < NK; j += 32) {
        float4 bj = sbox[j];
        float ja = sarea[j];
        int wmax = j >> 5;
        for (int wi = 0; wi <= wmax; wi++) {
            int i = wi * 32 + lane;              // <= 319, in padded range
            float4 bi = sbox[i];
            float lt0 = fmaxf(bi.x, bj.x), lt1 = fmaxf(bi.y, bj.y);
            float rb0 = fminf(bi.z, bj.z), rb1 = fminf(bi.w, bj.w);
            float iw = fmaxf(rb0 - lt0, 0.f), ih = fmaxf(rb1 - lt1, 0.f);
            float inter = iw * ih;
            float uni = fmaxf(sarea[i] + ja - inter, 1e-9f);
            bool sup = (i < j) && (inter > 0.3f * uni);
            unsigned m = __ballot_sync(FULLM, sup);
            if (lane == 0) colmask[j * NW + wi] = m;
        }
    }
    __syncthreads();

    // Parallel greedy NMS: iterate keep[j] = valid[j] & !exists(i<j kept, sup(i,j)).
    // Unique fixed point == greedy; converges in chain-depth iterations.
    // Only words w <= tid>>5 can hold suppressors (triangular).
    {
        if (tid < NW) kw[0][tid] = svalid[tid];
        __syncthreads();
        int cur = 0;
        bool myvalid = (tid < NK) && ((svalid[tid >> 5] >> (tid & 31)) & 1u);
        int mywmax = tid >> 5;                  // uniform within a warp
        for (int t = 0; t < NK + 2; t++) {
            if (tid == 0) schanged = 0;
            __syncthreads();
            bool kp = false;
            if (tid < NK) {
                unsigned sup = 0;
                for (int w = 0; w <= mywmax; w++)
                    sup |= colmask[tid * NW + w] & kw[cur][w];
                kp = myvalid && (sup == 0);
            }
            unsigned word = __ballot_sync(FULLM, kp);
            if (lane == 0 && wrp < NW) {
                kw[cur ^ 1][wrp] = word;
                if (word != kw[cur][wrp]) schanged = 1;
            }
            __syncthreads();
            if (!schanged) break;               // fixed point == greedy result
            cur ^= 1;
        }
        if (tid < NW) svalid[tid] = kw[cur][tid];   // final keep words
    }
    __syncthreads();

    // Outputs: [ids(4800) | boxes(19200) | labels(4800) | scores(4800) | keep(4800)]
    if (tid < NK) {
        bool keep = (svalid[tid >> 5] >> (tid & 31)) & 1u;
        int slot = b * NK + tid;
        float kf = keep ? 1.0f : 0.0f;
        float4 bx = sbox[tid];
        out[slot] = keep ? (float)b : -1.0f;
        float* ob = out + NB * NK + slot * 4;
        ob[0] = bx.x * kf;
        ob[1] = bx.y * kf;
        ob[2] = bx.z * kf;
        ob[3] = bx.w * kf;
        out[NB * NK * 5 + slot] = kf;
        out[NB * NK * 6 + slot] = ssc[tid] * kf;
        out[NB * NK * 7 + slot] = kf;
    }

    // Reset global scratch for next graph replay (module-load values also 0).
    for (int i = tid; i < NBINS; i += 1024) g_hist[b][i] = 0u;
    if (tid == 0) g_count[b] = 0;
}

extern "C" void kernel_launch(void* const* d_in, const int* in_sizes, int n_in,
                              void* d_out, int out_size) {
    const float* p_loc   = (const float*)d_in[0];
    const float* p_conf  = (const float*)d_in[1];
    // d_in[2] = p_landms: dead compute in reference, intentionally unread.
    const float* anchors = (const float*)d_in[3];
    float* out = (float*)d_out;

    k_scan<<<(NB * NA / 4) / 256, 256>>>((const float4*)p_conf);
    k_select<<<NB, 1024>>>(p_loc, anchors, out);
}